// round 1
// baseline (speedup 1.0000x reference)
#include <cuda_runtime.h>

#define D_DIM 64
#define H_DIM 256
#define W_DIM 256
#define PLANE (H_DIM * W_DIM)

// compare-exchange: a=min, b=max
__device__ __forceinline__ void s2(float& a, float& b) {
    float t = fminf(a, b);
    b = fmaxf(a, b);
    a = t;
}

// Min->v[0], max->v[K-1], all other values preserved (multiset).
// Cost ~1.5K-2 exchanges.
template <int K>
__device__ __forceinline__ void mnmxK(float* v) {
    constexpr int H2 = K / 2;
#pragma unroll
    for (int i = 0; i < H2; ++i) s2(v[i], v[i + H2]);
    if (K & 1) s2(v[0], v[K - 1]);
#pragma unroll
    for (int i = 1; i < H2; ++i) s2(v[0], v[i]);          // min chain
#pragma unroll
    for (int i = H2; i < K - 1; ++i) s2(v[i], v[K - 1]);  // max chain
}

// Exact median of 27 via forgetful selection (buffer 15).
__device__ __forceinline__ float median27(const float A[9], const float B[9], const float C[9]) {
    float m[15];
#pragma unroll
    for (int i = 0; i < 9; ++i) m[i] = A[i];
#pragma unroll
    for (int i = 0; i < 6; ++i) m[9 + i] = B[i];
    mnmxK<15>(m); m[0] = B[6];
    mnmxK<14>(m); m[0] = B[7];
    mnmxK<13>(m); m[0] = B[8];
    mnmxK<12>(m); m[0] = C[0];
    mnmxK<11>(m); m[0] = C[1];
    mnmxK<10>(m); m[0] = C[2];
    mnmxK<9>(m);  m[0] = C[3];
    mnmxK<8>(m);  m[0] = C[4];
    mnmxK<7>(m);  m[0] = C[5];
    mnmxK<6>(m);  m[0] = C[6];
    mnmxK<5>(m);  m[0] = C[7];
    mnmxK<4>(m);  m[0] = C[8];
    // median of the final 3 survivors m[0..2]
    float lo = fminf(m[0], m[1]);
    float hi = fmaxf(m[0], m[1]);
    return fmaxf(lo, fminf(hi, m[2]));
}

// Load the 3x3 (h,w) neighborhood of one D-plane with zero padding.
__device__ __forceinline__ void load9(const float* __restrict__ q, float* P,
                                      bool hm, bool hp, bool wm, bool wp) {
    P[0] = (hm && wm) ? __ldg(q - W_DIM - 1) : 0.0f;
    P[1] = (hm)       ? __ldg(q - W_DIM)     : 0.0f;
    P[2] = (hm && wp) ? __ldg(q - W_DIM + 1) : 0.0f;
    P[3] = (wm)       ? __ldg(q - 1)         : 0.0f;
    P[4] =              __ldg(q);
    P[5] = (wp)       ? __ldg(q + 1)         : 0.0f;
    P[6] = (hp && wm) ? __ldg(q + W_DIM - 1) : 0.0f;
    P[7] = (hp)       ? __ldg(q + W_DIM)     : 0.0f;
    P[8] = (hp && wp) ? __ldg(q + W_DIM + 1) : 0.0f;
}

__global__ void __launch_bounds__(128)
median3d_kernel(const float* __restrict__ x, float* __restrict__ y) {
    const int w = blockIdx.x * blockDim.x + threadIdx.x;  // 0..255
    const int h = blockIdx.y;                             // 0..255

    const bool wm = (w > 0), wp = (w < W_DIM - 1);
    const bool hm = (h > 0), hp = (h < H_DIM - 1);

    const float* p0 = x + (size_t)h * W_DIM + w;
    float* o0 = y + (size_t)h * W_DIM + w;

    float A[9], B[9], C[9];
#pragma unroll
    for (int i = 0; i < 9; ++i) A[i] = 0.0f;  // plane d = -1 (zero pad)

    load9(p0, B, hm, hp, wm, wp);             // plane d = 0

    for (int d = 0; d < D_DIM; ++d) {
        if (d + 1 < D_DIM) {
            load9(p0 + (size_t)(d + 1) * PLANE, C, hm, hp, wm, wp);
        } else {
#pragma unroll
            for (int i = 0; i < 9; ++i) C[i] = 0.0f;  // plane d = 64 (zero pad)
        }

        o0[(size_t)d * PLANE] = median27(A, B, C);

#pragma unroll
        for (int i = 0; i < 9; ++i) { A[i] = B[i]; B[i] = C[i]; }
    }
}

extern "C" void kernel_launch(void* const* d_in, const int* in_sizes, int n_in,
                              void* d_out, int out_size) {
    const float* x = (const float*)d_in[0];
    float* y = (float*)d_out;
    dim3 block(128, 1, 1);
    dim3 grid(W_DIM / 128, H_DIM, 1);  // (2, 256)
    median3d_kernel<<<grid, block>>>(x, y);
}

// round 2
// speedup vs baseline: 1.3475x; 1.3475x over previous
#include <cuda_runtime.h>

#define D_DIM 64
#define H_DIM 256
#define W_DIM 256
#define PLANE (H_DIM * W_DIM)
#define D_CHUNK 8

// compare-exchange: a=min, b=max
__device__ __forceinline__ void s2(float& a, float& b) {
    float t = fminf(a, b);
    b = fmaxf(a, b);
    a = t;
}

// Min->v[0], max->v[K-1], all other values preserved (multiset).
template <int K>
__device__ __forceinline__ void mnmxK(float* v) {
    constexpr int H2 = K / 2;
#pragma unroll
    for (int i = 0; i < H2; ++i) s2(v[i], v[i + H2]);
    if (K & 1) s2(v[0], v[K - 1]);
#pragma unroll
    for (int i = 1; i < H2; ++i) s2(v[0], v[i]);          // min chain
#pragma unroll
    for (int i = H2; i < K - 1; ++i) s2(v[i], v[K - 1]);  // max chain
}

// Exact median of 27 via forgetful selection (buffer 15).
__device__ __forceinline__ float median27(const float A[9], const float B[9], const float C[9]) {
    float m[15];
#pragma unroll
    for (int i = 0; i < 9; ++i) m[i] = A[i];
#pragma unroll
    for (int i = 0; i < 6; ++i) m[9 + i] = B[i];
    mnmxK<15>(m); m[0] = B[6];
    mnmxK<14>(m); m[0] = B[7];
    mnmxK<13>(m); m[0] = B[8];
    mnmxK<12>(m); m[0] = C[0];
    mnmxK<11>(m); m[0] = C[1];
    mnmxK<10>(m); m[0] = C[2];
    mnmxK<9>(m);  m[0] = C[3];
    mnmxK<8>(m);  m[0] = C[4];
    mnmxK<7>(m);  m[0] = C[5];
    mnmxK<6>(m);  m[0] = C[6];
    mnmxK<5>(m);  m[0] = C[7];
    mnmxK<4>(m);  m[0] = C[8];
    // median of the final 3 survivors m[0..2]
    float lo = fminf(m[0], m[1]);
    float hi = fmaxf(m[0], m[1]);
    return fmaxf(lo, fminf(hi, m[2]));
}

// Load the 3x3 (h,w) neighborhood of one D-plane with zero padding.
__device__ __forceinline__ void load9(const float* __restrict__ q, float* P,
                                      bool hm, bool hp, bool wm, bool wp) {
    P[0] = (hm && wm) ? __ldg(q - W_DIM - 1) : 0.0f;
    P[1] = (hm)       ? __ldg(q - W_DIM)     : 0.0f;
    P[2] = (hm && wp) ? __ldg(q - W_DIM + 1) : 0.0f;
    P[3] = (wm)       ? __ldg(q - 1)         : 0.0f;
    P[4] =              __ldg(q);
    P[5] = (wp)       ? __ldg(q + 1)         : 0.0f;
    P[6] = (hp && wm) ? __ldg(q + W_DIM - 1) : 0.0f;
    P[7] = (hp)       ? __ldg(q + W_DIM)     : 0.0f;
    P[8] = (hp && wp) ? __ldg(q + W_DIM + 1) : 0.0f;
}

__global__ void __launch_bounds__(256)
median3d_kernel(const float* __restrict__ x, float* __restrict__ y) {
    const int w = threadIdx.x;          // 0..255
    const int h = blockIdx.x;           // 0..255
    const int d0 = blockIdx.y * D_CHUNK;

    const bool wm = (w > 0), wp = (w < W_DIM - 1);
    const bool hm = (h > 0), hp = (h < H_DIM - 1);

    const float* p0 = x + (size_t)h * W_DIM + w;
    float* o0 = y + (size_t)h * W_DIM + w;

    float A[9], B[9], C[9];

    // plane d0-1 (zero pad if d0 == 0)
    if (d0 == 0) {
#pragma unroll
        for (int i = 0; i < 9; ++i) A[i] = 0.0f;
    } else {
        load9(p0 + (size_t)(d0 - 1) * PLANE, A, hm, hp, wm, wp);
    }

    // plane d0
    load9(p0 + (size_t)d0 * PLANE, B, hm, hp, wm, wp);

#pragma unroll
    for (int dd = 0; dd < D_CHUNK; ++dd) {
        const int d = d0 + dd;
        if (d + 1 < D_DIM) {
            load9(p0 + (size_t)(d + 1) * PLANE, C, hm, hp, wm, wp);
        } else {
#pragma unroll
            for (int i = 0; i < 9; ++i) C[i] = 0.0f;  // plane d = 64 (zero pad)
        }

        o0[(size_t)d * PLANE] = median27(A, B, C);

#pragma unroll
        for (int i = 0; i < 9; ++i) { A[i] = B[i]; B[i] = C[i]; }
    }
}

extern "C" void kernel_launch(void* const* d_in, const int* in_sizes, int n_in,
                              void* d_out, int out_size) {
    const float* x = (const float*)d_in[0];
    float* y = (float*)d_out;
    dim3 block(256, 1, 1);
    dim3 grid(H_DIM, D_DIM / D_CHUNK, 1);  // (256, 8)
    median3d_kernel<<<grid, block>>>(x, y);
}

// round 3
// speedup vs baseline: 1.7552x; 1.3026x over previous
#include <cuda_runtime.h>

#define D_DIM 64
#define H_DIM 256
#define W_DIM 256
#define PLANE (H_DIM * W_DIM)
#define D_CHUNK 4   // outputs per block along D (2 shared pairs)

// compare-exchange: a=min, b=max
__device__ __forceinline__ void s2(float& a, float& b) {
    float t = fminf(a, b);
    b = fmaxf(a, b);
    a = t;
}

// Min->v[0], max->v[K-1], all other values preserved as a multiset.
template <int K>
__device__ __forceinline__ void mnmxK(float* v) {
    constexpr int H2 = K / 2;
#pragma unroll
    for (int i = 0; i < H2; ++i) s2(v[i], v[i + H2]);
    if (K & 1) s2(v[0], v[K - 1]);
#pragma unroll
    for (int i = 1; i < H2; ++i) s2(v[0], v[i]);          // min chain
#pragma unroll
    for (int i = H2; i < K - 1; ++i) s2(v[i], v[K - 1]);  // max chain
}

// Forgetful front-end on the 18 shared values (planes P0,P1), buffer 15.
// Drops 4 mins + 4 maxes; S[0..9] = surviving middle multiset.
// Safety: every dropped min/max has >=14 elements of the eventual 27-set on
// the other side (bufsize-1 + prior drops == 14 at every round), so none can
// be the median of (P0,P1,X) for ANY third plane X.
__device__ __forceinline__ void mid10(const float* P0, const float* P1, float* S) {
    float m[15];
#pragma unroll
    for (int i = 0; i < 9; ++i) m[i] = P0[i];
#pragma unroll
    for (int i = 0; i < 6; ++i) m[9 + i] = P1[i];
    mnmxK<15>(m); m[0] = P1[6];
    mnmxK<14>(m); m[0] = P1[7];
    mnmxK<13>(m); m[0] = P1[8];
    mnmxK<12>(m);
#pragma unroll
    for (int i = 0; i < 10; ++i) S[i] = m[1 + i];
}

// Median of the 19 values {S[0..9]} ∪ {A[0..8]} == median of the full 27.
__device__ __forceinline__ float median19(const float* S, const float* A) {
    float b[11];
    b[0] = A[0];
#pragma unroll
    for (int i = 0; i < 10; ++i) b[1 + i] = S[i];
    mnmxK<11>(b); b[0] = A[1];
    mnmxK<10>(b); b[0] = A[2];
    mnmxK<9>(b);  b[0] = A[3];
    mnmxK<8>(b);  b[0] = A[4];
    mnmxK<7>(b);  b[0] = A[5];
    mnmxK<6>(b);  b[0] = A[6];
    mnmxK<5>(b);  b[0] = A[7];
    mnmxK<4>(b);  b[0] = A[8];
    // survivors b[1], b[2], plus last insert b[0]
    float lo = fminf(b[0], b[1]);
    float hi = fmaxf(b[0], b[1]);
    return fmaxf(lo, fminf(hi, b[2]));
}

// Load the 3x3 (h,w) neighborhood of one D-plane with zero padding.
__device__ __forceinline__ void load9(const float* __restrict__ q, float* P,
                                      bool hm, bool hp, bool wm, bool wp) {
    P[0] = (hm && wm) ? __ldg(q - W_DIM - 1) : 0.0f;
    P[1] = (hm)       ? __ldg(q - W_DIM)     : 0.0f;
    P[2] = (hm && wp) ? __ldg(q - W_DIM + 1) : 0.0f;
    P[3] = (wm)       ? __ldg(q - 1)         : 0.0f;
    P[4] =              __ldg(q);
    P[5] = (wp)       ? __ldg(q + 1)         : 0.0f;
    P[6] = (hp && wm) ? __ldg(q + W_DIM - 1) : 0.0f;
    P[7] = (hp)       ? __ldg(q + W_DIM)     : 0.0f;
    P[8] = (hp && wp) ? __ldg(q + W_DIM + 1) : 0.0f;
}

__global__ void __launch_bounds__(256)
median3d_kernel(const float* __restrict__ x, float* __restrict__ y) {
    const int w = threadIdx.x;          // 0..255
    const int h = blockIdx.x;           // 0..255
    const int d0 = blockIdx.y * D_CHUNK;

    const bool wm = (w > 0), wp = (w < W_DIM - 1);
    const bool hm = (h > 0), hp = (h < H_DIM - 1);

    const float* p0 = x + (size_t)h * W_DIM + w;
    float* o0 = y + (size_t)h * W_DIM + w;

    float Pm[9], P0[9], P1[9], P2[9], S[10];

    // plane d0-1 (zero pad if d0 == 0)
    if (d0 == 0) {
#pragma unroll
        for (int i = 0; i < 9; ++i) Pm[i] = 0.0f;
    } else {
        load9(p0 + (size_t)(d0 - 1) * PLANE, Pm, hm, hp, wm, wp);
    }
    // plane d0
    load9(p0 + (size_t)d0 * PLANE, P0, hm, hp, wm, wp);

#pragma unroll
    for (int pp = 0; pp < D_CHUNK / 2; ++pp) {
        const int d = d0 + 2 * pp;     // pair (d, d+1); d+1 <= 63 always

        // plane d+1 (always exists: d <= 62)
        load9(p0 + (size_t)(d + 1) * PLANE, P1, hm, hp, wm, wp);

        // plane d+2 (zero pad if d+2 == D_DIM)
        if (d + 2 < D_DIM) {
            load9(p0 + (size_t)(d + 2) * PLANE, P2, hm, hp, wm, wp);
        } else {
#pragma unroll
            for (int i = 0; i < 9; ++i) P2[i] = 0.0f;
        }

        // shared middle-10 of planes (d, d+1)
        mid10(P0, P1, S);

        // two independent tails (good ILP)
        o0[(size_t)d * PLANE]       = median19(S, Pm);
        o0[(size_t)(d + 1) * PLANE] = median19(S, P2);

        // slide by 2: Pm <- P1, P0 <- P2
#pragma unroll
        for (int i = 0; i < 9; ++i) { Pm[i] = P1[i]; P0[i] = P2[i]; }
    }
}

extern "C" void kernel_launch(void* const* d_in, const int* in_sizes, int n_in,
                              void* d_out, int out_size) {
    const float* x = (const float*)d_in[0];
    float* y = (float*)d_out;
    dim3 block(256, 1, 1);
    dim3 grid(H_DIM, D_DIM / D_CHUNK, 1);  // (256, 16)
    median3d_kernel<<<grid, block>>>(x, y);
}

// round 4
// speedup vs baseline: 2.9980x; 1.7080x over previous
#include <cuda_runtime.h>

#define D_DIM 64
#define H_DIM 256
#define W_DIM 256
#define PLANE (H_DIM * W_DIM)
#define D_CHUNK 8   // outputs per block along D (4 shared pairs)

// compare-exchange: a=min, b=max
__device__ __forceinline__ void s2(float& a, float& b) {
    float t = fminf(a, b);
    b = fmaxf(a, b);
    a = t;
}

// Optimal 9-input sorting network: 25 comparators, depth 7 (SorterHunter/Best).
__device__ __forceinline__ void sort9(float* v) {
    s2(v[0],v[3]); s2(v[1],v[7]); s2(v[2],v[5]); s2(v[4],v[8]);
    s2(v[0],v[7]); s2(v[2],v[4]); s2(v[3],v[8]); s2(v[5],v[6]);
    s2(v[0],v[2]); s2(v[1],v[3]); s2(v[4],v[5]); s2(v[7],v[8]);
    s2(v[1],v[4]); s2(v[3],v[6]); s2(v[5],v[7]);
    s2(v[0],v[1]); s2(v[2],v[4]); s2(v[3],v[5]); s2(v[6],v[8]);
    s2(v[2],v[3]); s2(v[4],v[5]); s2(v[6],v[7]);
    s2(v[1],v[2]); s2(v[3],v[4]); s2(v[5],v[6]);
}

// ---- Batcher odd-even merges of two sorted arrays ----
__device__ __forceinline__ void merge11(const float* a, const float* b, float* c) {
    c[0] = a[0]; c[1] = b[0]; s2(c[0], c[1]);
}
__device__ __forceinline__ void merge22(const float* a, const float* b, float* c) {
    float ae[1] = {a[0]}, be[1] = {b[0]}, ao[1] = {a[1]}, bo[1] = {b[1]};
    float e[2], o[2];
    merge11(ae, be, e); merge11(ao, bo, o);
    c[0] = e[0];
    c[1] = o[0]; c[2] = e[1]; s2(c[1], c[2]);
    c[3] = o[1];
}
__device__ __forceinline__ void merge33(const float* a, const float* b, float* c) {
    float ae[2] = {a[0], a[2]}, be[2] = {b[0], b[2]};
    float ao[1] = {a[1]},       bo[1] = {b[1]};
    float e[4], o[2];
    merge22(ae, be, e); merge11(ao, bo, o);
    c[0] = e[0];
    c[1] = o[0]; c[2] = e[1]; s2(c[1], c[2]);
    c[3] = o[1]; c[4] = e[2]; s2(c[3], c[4]);
    c[5] = e[3];
}
__device__ __forceinline__ void merge44(const float* a, const float* b, float* c) {
    float ae[2] = {a[0], a[2]}, be[2] = {b[0], b[2]};
    float ao[2] = {a[1], a[3]}, bo[2] = {b[1], b[3]};
    float e[4], o[4];
    merge22(ae, be, e); merge22(ao, bo, o);
    c[0] = e[0];
    c[1] = o[0]; c[2] = e[1]; s2(c[1], c[2]);
    c[3] = o[1]; c[4] = e[2]; s2(c[3], c[4]);
    c[5] = o[2]; c[6] = e[3]; s2(c[5], c[6]);
    c[7] = o[3];
}
__device__ __forceinline__ void merge55(const float* a, const float* b, float* c) {
    float ae[3] = {a[0], a[2], a[4]}, be[3] = {b[0], b[2], b[4]};
    float ao[2] = {a[1], a[3]},       bo[2] = {b[1], b[3]};
    float e[6], o[4];
    merge33(ae, be, e); merge22(ao, bo, o);
    c[0] = e[0];
#pragma unroll
    for (int i = 1; i <= 4; ++i) { c[2*i-1] = o[i-1]; c[2*i] = e[i]; s2(c[2*i-1], c[2*i]); }
    c[9] = e[5];
}
// Full merge of two sorted 9s into sorted 18 (30 comparators).
__device__ __forceinline__ void merge99(const float* a, const float* b, float* c) {
    float ae[5] = {a[0], a[2], a[4], a[6], a[8]};
    float be[5] = {b[0], b[2], b[4], b[6], b[8]};
    float ao[4] = {a[1], a[3], a[5], a[7]};
    float bo[4] = {b[1], b[3], b[5], b[7]};
    float e[10], o[8];
    merge55(ae, be, e); merge44(ao, bo, o);
    c[0] = e[0];
#pragma unroll
    for (int i = 1; i <= 8; ++i) { c[2*i-1] = o[i-1]; c[2*i] = e[i]; s2(c[2*i-1], c[2*i]); }
    c[17] = e[9];
}

// 10th smallest of sorted X[0..8] ∪ sorted T[0..9]  (== median of the 27-window:
// T = middle 10 of the merged shared pair, X = sorted outer plane).
// Closed form: max( T[0], max_i min(X[i], T[9-i]) ).
__device__ __forceinline__ float select10(const float* X, const float* T) {
    float c0 = T[0];
    float c1 = fminf(X[0], T[9]);
    float c2 = fminf(X[1], T[8]);
    float c3 = fminf(X[2], T[7]);
    float c4 = fminf(X[3], T[6]);
    float c5 = fminf(X[4], T[5]);
    float c6 = fminf(X[5], T[4]);
    float c7 = fminf(X[6], T[3]);
    float c8 = fminf(X[7], T[2]);
    float c9 = fminf(X[8], T[1]);
    float m01 = fmaxf(c0, c1), m23 = fmaxf(c2, c3);
    float m45 = fmaxf(c4, c5), m67 = fmaxf(c6, c7);
    float m89 = fmaxf(c8, c9);
    return fmaxf(fmaxf(fmaxf(m01, m23), fmaxf(m45, m67)), m89);
}

// Load the 3x3 (h,w) neighborhood of one D-plane with zero padding.
__device__ __forceinline__ void load9(const float* __restrict__ q, float* P,
                                      bool hm, bool hp, bool wm, bool wp) {
    P[0] = (hm && wm) ? __ldg(q - W_DIM - 1) : 0.0f;
    P[1] = (hm)       ? __ldg(q - W_DIM)     : 0.0f;
    P[2] = (hm && wp) ? __ldg(q - W_DIM + 1) : 0.0f;
    P[3] = (wm)       ? __ldg(q - 1)         : 0.0f;
    P[4] =              __ldg(q);
    P[5] = (wp)       ? __ldg(q + 1)         : 0.0f;
    P[6] = (hp && wm) ? __ldg(q + W_DIM - 1) : 0.0f;
    P[7] = (hp)       ? __ldg(q + W_DIM)     : 0.0f;
    P[8] = (hp && wp) ? __ldg(q + W_DIM + 1) : 0.0f;
}

__global__ void __launch_bounds__(256)
median3d_kernel(const float* __restrict__ x, float* __restrict__ y) {
    const int w = threadIdx.x;          // 0..255
    const int h = blockIdx.x;           // 0..255
    const int d0 = blockIdx.y * D_CHUNK;

    const bool wm = (w > 0), wp = (w < W_DIM - 1);
    const bool hm = (h > 0), hp = (h < H_DIM - 1);

    const float* p0 = x + (size_t)h * W_DIM + w;
    float* o0 = y + (size_t)h * W_DIM + w;

    float Pm[9], P0[9], P1[9], P2[9];   // sorted planes d-1, d, d+1, d+2
    float c[18];                        // merged pair (d, d+1)

    // plane d0-1 (zero pad if d0 == 0) — sorted
    if (d0 == 0) {
#pragma unroll
        for (int i = 0; i < 9; ++i) Pm[i] = 0.0f;
    } else {
        load9(p0 + (size_t)(d0 - 1) * PLANE, Pm, hm, hp, wm, wp);
        sort9(Pm);
    }
    // plane d0 — sorted
    load9(p0 + (size_t)d0 * PLANE, P0, hm, hp, wm, wp);
    sort9(P0);

#pragma unroll
    for (int pp = 0; pp < D_CHUNK / 2; ++pp) {
        const int d = d0 + 2 * pp;      // pair (d, d+1); d <= 62

        // plane d+1 (always exists) — sorted
        load9(p0 + (size_t)(d + 1) * PLANE, P1, hm, hp, wm, wp);
        sort9(P1);

        // plane d+2 (zero pad if d+2 == D_DIM) — sorted
        if (d + 2 < D_DIM) {
            load9(p0 + (size_t)(d + 2) * PLANE, P2, hm, hp, wm, wp);
            sort9(P2);
        } else {
#pragma unroll
            for (int i = 0; i < 9; ++i) P2[i] = 0.0f;
        }

        // shared sorted merge of planes (d, d+1); middle 10 = c[4..13]
        merge99(P0, P1, c);

        // two independent rank selections (high ILP)
        o0[(size_t)d * PLANE]       = select10(Pm, c + 4);
        o0[(size_t)(d + 1) * PLANE] = select10(P2, c + 4);

        // slide by 2: Pm <- P1, P0 <- P2 (register-renamed under full unroll)
#pragma unroll
        for (int i = 0; i < 9; ++i) { Pm[i] = P1[i]; P0[i] = P2[i]; }
    }
}

extern "C" void kernel_launch(void* const* d_in, const int* in_sizes, int n_in,
                              void* d_out, int out_size) {
    const float* x = (const float*)d_in[0];
    float* y = (float*)d_out;
    dim3 block(256, 1, 1);
    dim3 grid(H_DIM, D_DIM / D_CHUNK, 1);  // (256, 8)
    median3d_kernel<<<grid, block>>>(x, y);
}